// round 15
// baseline (speedup 1.0000x reference)
#include <cuda_runtime.h>
#include <cstdint>

#define BATCHN 4096
#define NI 784
#define NIP 800
#define WID 16000
#define WIDP 16384
#define NHID 4
#define NLAYERS 5
#define NCLS 10
#define NSLICE (BATCHN / 32)
#define GROUP (WID / NCLS)       // 1600
#define RW 3                     // reduce warps per class
#define RCHUNK ((GROUP + RW*32 - 1) / (RW*32))   // 17 words per lane

// Descriptor: ia | ib<<14 | na<<31 | nb<<30 ; pads read spread banks.
__device__ uint32_t g_gidx[NLAYERS][WIDP];

static __device__ __forceinline__ uint32_t read_bool(const void* __restrict__ p,
                                                     size_t e, int mode) {
    if (mode == 1) return ((const uint32_t*)p)[e] != 0u;
    if (mode == 0) return ((const uint8_t*)p)[e] != 0u;
    return ((const uint16_t*)p)[e] != 0u;
}

static __device__ __forceinline__ int mode_from_words(const uint32_t* w64v) {
    bool w32 = true, bf16 = true, u8 = true;
    for (int i = 0; i < 64; i++) {
        uint32_t w = w64v[i];
        if (!(w == 0u || w == 1u || w == 0x3F800000u)) w32 = false;
        uint32_t h0 = w & 0xFFFFu, h1 = w >> 16;
        if (!((h0 == 0u || h0 == 0x3F80u) && (h1 == 0u || h1 == 0x3F80u))) bf16 = false;
        if ((w & 0xFEFEFEFEu) != 0u) u8 = false;
    }
    return w32 ? 1 : (bf16 ? 2 : (u8 ? 0 : 1));
}

// ---------------------------------------------------------------------------
__global__ void prep_idx_k(const void* __restrict__ x,
                           const int* __restrict__ ia0, const int* __restrict__ ib0,
                           const void* __restrict__ ng0,
                           const int* __restrict__ iah, const int* __restrict__ ibh,
                           const void* __restrict__ ngh) {
    __shared__ int s_mode;
    if (threadIdx.x == 0) {
        uint32_t w[64];
        const uint32_t* xw = (const uint32_t*)x;
#pragma unroll
        for (int i = 0; i < 64; i++) w[i] = xw[i];
        s_mode = mode_from_words(w);
    }
    __syncthreads();
    int mode = s_mode;

    int t = blockIdx.x * blockDim.x + threadIdx.x;
    if (t >= NLAYERS * WIDP) return;
    int layer = t / WIDP;
    int n = t - layer * WIDP;
    uint32_t d;
    if (n < WID) {
        uint32_t ia, ib, na, nb;
        if (layer == 0) {
            ia = (uint32_t)ia0[n];
            ib = (uint32_t)ib0[n];
            na = read_bool(ng0, 2 * (size_t)n, mode);
            nb = read_bool(ng0, 2 * (size_t)n + 1, mode);
        } else {
            int k = layer - 1;
            ia = (uint32_t)iah[(size_t)k * WID + n];
            ib = (uint32_t)ibh[(size_t)k * WID + n];
            na = read_bool(ngh, ((size_t)k * WID + n) * 2, mode);
            nb = read_bool(ngh, ((size_t)k * WID + n) * 2 + 1, mode);
        }
        d = ia | (ib << 14) | (na << 31) | (nb << 30);
    } else {
        uint32_t sp = (uint32_t)(n & 31);      // pads: spread banks, no negs
        d = sp | (sp << 14);
    }
    g_gidx[layer][n] = d;
}

// ---------------------------------------------------------------------------
// Gate: (a ^ ma) & (b ^ mb); ma from bit 31, mb from bit 30 (sign-extends).
// ---------------------------------------------------------------------------
static __device__ __forceinline__ uint32_t gate(uint32_t d,
                                                const uint32_t* __restrict__ hs) {
    uint32_t a = hs[d & 0x3FFFu];
    uint32_t b = hs[(d >> 14) & 0x3FFFu];
    uint32_t ma = (uint32_t)(((int32_t)d) >> 31);
    uint32_t mb = (uint32_t)(((int32_t)(d << 1)) >> 31);
    return (a ^ ma) & (b ^ mb);
}

static __device__ __forceinline__ uint4 gate4(uint4 d, const uint32_t* __restrict__ hs) {
    uint4 r;
    r.x = gate(d.x, hs);
    r.y = gate(d.y, hs);
    r.z = gate(d.z, hs);
    r.w = gate(d.w, hs);
    return r;
}

// ---------------------------------------------------------------------------
#define SM_BUF 16384
#define SM_WORDS (2 * SM_BUF + NI)
#define SM_BYTES (SM_WORDS * 4)

__global__ void __launch_bounds__(1024) fused_k(const void* __restrict__ x,
                                                float* __restrict__ out) {
    extern __shared__ uint32_t sm[];
    uint32_t* h0 = sm;
    uint32_t* h1 = sm + SM_BUF;
    uint32_t* xp = sm + 2 * SM_BUF;
    uint8_t*  stg = (uint8_t*)h1;
    __shared__ int partial[NCLS][RW][32];
    __shared__ int s_mode;

    int s = blockIdx.x;
    int t = threadIdx.x;
    int wid = t >> 5;
    int lane = t & 31;

    // Layer-0 descriptors: issued first, latency hidden behind the pack.
    const uint4* gl = (const uint4*)g_gidx[0];
    uint4 d0 = gl[t];
    uint4 d1 = gl[1024 + t];
    uint4 d2 = gl[2048 + t];
    uint4 d3 = gl[3072 + t];

    // --- mode detection ---
    if (t < 64) xp[t] = ((const uint32_t*)x)[t];
    __syncthreads();
    if (t == 0) s_mode = mode_from_words(xp);
    __syncthreads();
    int mode = s_mode;

    // --- Phase A: coalesced row loads. warp = sample row, lanes stride. ---
    {
        size_t rowbase = (size_t)(32 * s + wid) * NI;
        uint8_t* rowdst = stg + wid * NIP;
        for (int i = lane; i < NI; i += 32)
            rowdst[i] = (uint8_t)read_bool(x, rowbase + i, mode);
    }
    __syncthreads();

    // --- Phase B: transpose bytes -> packed words xp[i]. ---
    if (t < NI) {
        uint32_t acc = 0;
#pragma unroll
        for (int j = 0; j < 32; j++)
            acc |= (uint32_t)stg[j * NIP + t] << j;
        xp[t] = acc;
    }
    __syncthreads();

    // --- 5 layers, unrolled; src/dst ping-pong (R13 body: measured best) ---
#pragma unroll
    for (int L = 0; L < NLAYERS; L++) {
        const uint32_t* hs = (L == 0) ? xp : ((L & 1) ? h0 : h1);
        uint4* hd4 = (uint4*)((L & 1) ? h1 : h0);

        uint4 r0 = gate4(d0, hs);
        uint4 r1 = gate4(d1, hs);
        uint4 r2 = gate4(d2, hs);
        uint4 r3 = gate4(d3, hs);
        hd4[t] = r0;
        hd4[1024 + t] = r1;
        hd4[2048 + t] = r2;
        hd4[3072 + t] = r3;

        if (L + 1 < NLAYERS) {       // prefetch next layer's descriptors
            const uint4* gn = (const uint4*)g_gidx[L + 1];
            d0 = gn[t];
            d1 = gn[1024 + t];
            d2 = gn[2048 + t];
            d3 = gn[3072 + t];
        }
        __syncthreads();
    }

    // --- In-CTA GroupSum from h0: 30 warps, 3 per class, 17 words/lane ---
    if (wid < RW * NCLS) {
        int c = wid / RW;
        int ch = wid - c * RW;
        int base = ch * RCHUNK * 32;            // 0, 544, 1088
        int nwords = (base + RCHUNK * 32 <= GROUP) ? RCHUNK
                                                   : (GROUP - base + 31) / 32;
        const uint32_t* __restrict__ p = h0 + c * GROUP + base + lane;
        uint32_t s0 = 0, s1 = 0, s2 = 0, s3 = 0, s4 = 0;
        for (int k = 0; k < nwords; k++) {
            uint32_t cc = p[k * 32];
            uint32_t tt;
            tt = s0 & cc; s0 ^= cc; cc = tt;
            tt = s1 & cc; s1 ^= cc; cc = tt;
            tt = s2 & cc; s2 ^= cc; cc = tt;
            tt = s3 & cc; s3 ^= cc; cc = tt;
            s4 ^= cc;                            // counts <= 17 < 32
        }
#pragma unroll
        for (int b = 0; b < 32; b++) {
            int tot = __popc(__ballot_sync(0xFFFFFFFFu, (s0 >> b) & 1u))
                    + 2  * __popc(__ballot_sync(0xFFFFFFFFu, (s1 >> b) & 1u))
                    + 4  * __popc(__ballot_sync(0xFFFFFFFFu, (s2 >> b) & 1u))
                    + 8  * __popc(__ballot_sync(0xFFFFFFFFu, (s3 >> b) & 1u))
                    + 16 * __popc(__ballot_sync(0xFFFFFFFFu, (s4 >> b) & 1u));
            if (lane == b) partial[c][ch][b] = tot;
        }
    }
    __syncthreads();

    if (t < NCLS * 32) {
        int c = t >> 5;
        int b = t & 31;
        out[(size_t)(s * 32 + b) * NCLS + c] =
            (float)(partial[c][0][b] + partial[c][1][b] + partial[c][2][b]);
    }
}

// ---------------------------------------------------------------------------
// Bind inputs BY ELEMENT COUNT. Output: float32 [BATCH, NCLS]
// ---------------------------------------------------------------------------
extern "C" void kernel_launch(void* const* d_in, const int* in_sizes, int n_in,
                              void* d_out, int out_size) {
    const void* x = nullptr;
    const int *ia0 = nullptr, *ib0 = nullptr, *iah = nullptr, *ibh = nullptr;
    const void *ng0 = nullptr, *ngh = nullptr;

    for (int i = 0; i < n_in; i++) {
        int sz = in_sizes[i];
        if (sz == BATCHN * NI) {
            x = d_in[i];
        } else if (sz == WID) {
            if (!ia0) ia0 = (const int*)d_in[i]; else ib0 = (const int*)d_in[i];
        } else if (sz == WID * 2) {
            ng0 = d_in[i];
        } else if (sz == NHID * WID) {
            if (!iah) iah = (const int*)d_in[i]; else ibh = (const int*)d_in[i];
        } else if (sz == NHID * WID * 2) {
            ngh = d_in[i];
        }
    }
    float* out = (float*)d_out;

    static bool attr_set = false;
    if (!attr_set) {
        cudaFuncSetAttribute(fused_k, cudaFuncAttributeMaxDynamicSharedMemorySize,
                             SM_BYTES);
        attr_set = true;
    }

    prep_idx_k<<<(NLAYERS * WIDP + 511) / 512, 512>>>(x, ia0, ib0, ng0, iah, ibh, ngh);

    fused_k<<<NSLICE, 1024, SM_BYTES>>>(x, out);
}

// round 16
// speedup vs baseline: 1.1454x; 1.1454x over previous
#include <cuda_runtime.h>
#include <cstdint>

#define BATCHN 4096
#define NI 784
#define NIP 800
#define WID 16000
#define WIDP 16384
#define NHID 4
#define NLAYERS 5
#define NCLS 10
#define NSLICE (BATCHN / 32)
#define GROUP (WID / NCLS)
#define HGRP (GROUP / 2)
#define KWORDS (HGRP / 32)

// Descriptor: ia | ib<<14 | na<<31 | nb<<30 ; pad entries are 0 (harmless).
__device__ uint32_t g_gidx[NLAYERS][WIDP];

static __device__ __forceinline__ uint32_t read_bool(const void* __restrict__ p,
                                                     size_t e, int mode) {
    if (mode == 1) return ((const uint32_t*)p)[e] != 0u;
    if (mode == 0) return ((const uint8_t*)p)[e] != 0u;
    return ((const uint16_t*)p)[e] != 0u;
}

static __device__ __forceinline__ int mode_from_words(const uint32_t* w64v) {
    bool w32 = true, bf16 = true, u8 = true;
    for (int i = 0; i < 64; i++) {
        uint32_t w = w64v[i];
        if (!(w == 0u || w == 1u || w == 0x3F800000u)) w32 = false;
        uint32_t h0 = w & 0xFFFFu, h1 = w >> 16;
        if (!((h0 == 0u || h0 == 0x3F80u) && (h1 == 0u || h1 == 0x3F80u))) bf16 = false;
        if ((w & 0xFEFEFEFEu) != 0u) u8 = false;
    }
    return w32 ? 1 : (bf16 ? 2 : (u8 ? 0 : 1));
}

// ---------------------------------------------------------------------------
// prep_idx_k: pack descriptors for all 5 layers, padded to WIDP.
// Triggers PDL completion early so fused_k can start its pack phase
// concurrently; fused_k gates on full prep completion via
// cudaGridDependencySynchronize().
// ---------------------------------------------------------------------------
__global__ void prep_idx_k(const void* __restrict__ x,
                           const int* __restrict__ ia0, const int* __restrict__ ib0,
                           const void* __restrict__ ng0,
                           const int* __restrict__ iah, const int* __restrict__ ibh,
                           const void* __restrict__ ngh) {
#if __CUDA_ARCH__ >= 900
    if (threadIdx.x == 0) cudaTriggerProgrammaticLaunchCompletion();
#endif
    __shared__ int s_mode;
    if (threadIdx.x == 0) {
        uint32_t w[64];
        const uint32_t* xw = (const uint32_t*)x;
#pragma unroll
        for (int i = 0; i < 64; i++) w[i] = xw[i];
        s_mode = mode_from_words(w);
    }
    __syncthreads();
    int mode = s_mode;

    int t = blockIdx.x * blockDim.x + threadIdx.x;
    if (t >= NLAYERS * WIDP) return;
    int layer = t / WIDP;
    int n = t - layer * WIDP;
    uint32_t d = 0;
    if (n < WID) {
        uint32_t ia, ib, na, nb;
        if (layer == 0) {
            ia = (uint32_t)ia0[n];
            ib = (uint32_t)ib0[n];
            na = read_bool(ng0, 2 * (size_t)n, mode);
            nb = read_bool(ng0, 2 * (size_t)n + 1, mode);
        } else {
            int k = layer - 1;
            ia = (uint32_t)iah[(size_t)k * WID + n];
            ib = (uint32_t)ibh[(size_t)k * WID + n];
            na = read_bool(ngh, ((size_t)k * WID + n) * 2, mode);
            nb = read_bool(ngh, ((size_t)k * WID + n) * 2 + 1, mode);
        }
        d = ia | (ib << 14) | (na << 31) | (nb << 30);
    }
    g_gidx[layer][n] = d;
}

// ---------------------------------------------------------------------------
// Gate: (a ^ ma) & (b ^ mb); ma from bit 31, mb from bit 30 (sign-extends).
// ---------------------------------------------------------------------------
static __device__ __forceinline__ uint32_t gate(uint32_t d,
                                                const uint32_t* __restrict__ hs) {
    uint32_t a = hs[d & 0x3FFFu];
    uint32_t b = hs[(d >> 14) & 0x3FFFu];
    uint32_t ma = (uint32_t)(((int32_t)d) >> 31);
    uint32_t mb = (uint32_t)(((int32_t)(d << 1)) >> 31);
    return (a ^ ma) & (b ^ mb);
}

static __device__ __forceinline__ uint4 gate4(uint4 d, const uint32_t* __restrict__ hs) {
    uint4 r;
    r.x = gate(d.x, hs);
    r.y = gate(d.y, hs);
    r.z = gate(d.z, hs);
    r.w = gate(d.w, hs);
    return r;
}

// ---------------------------------------------------------------------------
// fused_k: R13 body verbatim, except the layer-0 descriptor loads sit after
// cudaGridDependencySynchronize() (PDL join with prep_idx_k).
// ---------------------------------------------------------------------------
#define SM_BUF 16384
#define SM_WORDS (2 * SM_BUF + NI)
#define SM_BYTES (SM_WORDS * 4)

__global__ void __launch_bounds__(1024) fused_k(const void* __restrict__ x,
                                                float* __restrict__ out) {
    extern __shared__ uint32_t sm[];
    uint32_t* h0 = sm;
    uint32_t* h1 = sm + SM_BUF;
    uint32_t* xp = sm + 2 * SM_BUF;
    uint8_t*  stg = (uint8_t*)h1;           // 32 x NIP bytes, dies before L=1
    __shared__ int partial[NCLS][2][32];
    __shared__ int s_mode;

    int s = blockIdx.x;
    int t = threadIdx.x;
    int wid = t >> 5;
    int lane = t & 31;

    // --- mode detection (reads only x; safe before PDL join) ---
    if (t < 64) xp[t] = ((const uint32_t*)x)[t];
    __syncthreads();
    if (t == 0) s_mode = mode_from_words(xp);
    __syncthreads();
    int mode = s_mode;

    // --- Phase A: coalesced row loads. warp = sample row, lanes stride. ---
    {
        size_t rowbase = (size_t)(32 * s + wid) * NI;
        uint8_t* rowdst = stg + wid * NIP;
        for (int i = lane; i < NI; i += 32)
            rowdst[i] = (uint8_t)read_bool(x, rowbase + i, mode);
    }
    __syncthreads();

    // --- Phase B: transpose bytes -> packed words xp[i]. ---
    if (t < NI) {
        uint32_t acc = 0;
#pragma unroll
        for (int j = 0; j < 32; j++)
            acc |= (uint32_t)stg[j * NIP + t] << j;
        xp[t] = acc;
    }
    __syncthreads();

    // --- PDL join: g_gidx must be complete from here on. ---
#if __CUDA_ARCH__ >= 900
    cudaGridDependencySynchronize();
#endif

    const uint4* gl = (const uint4*)g_gidx[0];
    uint4 d0 = gl[t];
    uint4 d1 = gl[1024 + t];
    uint4 d2 = gl[2048 + t];
    uint4 d3 = gl[3072 + t];

    // --- 5 layers, unrolled; src/dst ping-pong; prefetch next descriptors ---
#pragma unroll
    for (int L = 0; L < NLAYERS; L++) {
        const uint32_t* hs = (L == 0) ? xp : ((L & 1) ? h0 : h1);
        uint4* hd4 = (uint4*)((L & 1) ? h1 : h0);

        uint4 r0 = gate4(d0, hs);
        uint4 r1 = gate4(d1, hs);
        uint4 r2 = gate4(d2, hs);
        uint4 r3 = gate4(d3, hs);
        hd4[t] = r0;
        hd4[1024 + t] = r1;
        hd4[2048 + t] = r2;
        hd4[3072 + t] = r3;

        if (L + 1 < NLAYERS) {
            const uint4* gn = (const uint4*)g_gidx[L + 1];
            d0 = gn[t];
            d1 = gn[1024 + t];
            d2 = gn[2048 + t];
            d3 = gn[3072 + t];
        }
        __syncthreads();
    }

    // --- In-CTA GroupSum from h0 (R13 reduce: 20 warps, 25 words/lane) ---
    if (wid < 2 * NCLS) {
        int c = wid >> 1;
        int hf = wid & 1;
        const uint32_t* __restrict__ p = h0 + c * GROUP + hf * HGRP + lane;
        uint32_t s0 = 0, s1 = 0, s2 = 0, s3 = 0, s4 = 0;
#pragma unroll
        for (int k = 0; k < KWORDS; k++) {
            uint32_t cc = p[k * 32];
            uint32_t tt;
            tt = s0 & cc; s0 ^= cc; cc = tt;
            tt = s1 & cc; s1 ^= cc; cc = tt;
            tt = s2 & cc; s2 ^= cc; cc = tt;
            tt = s3 & cc; s3 ^= cc; cc = tt;
            s4 ^= cc;
        }
#pragma unroll
        for (int b = 0; b < 32; b++) {
            int tot = __popc(__ballot_sync(0xFFFFFFFFu, (s0 >> b) & 1u))
                    + 2  * __popc(__ballot_sync(0xFFFFFFFFu, (s1 >> b) & 1u))
                    + 4  * __popc(__ballot_sync(0xFFFFFFFFu, (s2 >> b) & 1u))
                    + 8  * __popc(__ballot_sync(0xFFFFFFFFu, (s3 >> b) & 1u))
                    + 16 * __popc(__ballot_sync(0xFFFFFFFFu, (s4 >> b) & 1u));
            if (lane == b) partial[c][hf][b] = tot;
        }
    }
    __syncthreads();

    if (t < NCLS * 32) {
        int c = t >> 5;
        int b = t & 31;
        out[(size_t)(s * 32 + b) * NCLS + c] =
            (float)(partial[c][0][b] + partial[c][1][b]);
    }
}

// ---------------------------------------------------------------------------
// Bind inputs BY ELEMENT COUNT. Output: float32 [BATCH, NCLS]
// ---------------------------------------------------------------------------
extern "C" void kernel_launch(void* const* d_in, const int* in_sizes, int n_in,
                              void* d_out, int out_size) {
    const void* x = nullptr;
    const int *ia0 = nullptr, *ib0 = nullptr, *iah = nullptr, *ibh = nullptr;
    const void *ng0 = nullptr, *ngh = nullptr;

    for (int i = 0; i < n_in; i++) {
        int sz = in_sizes[i];
        if (sz == BATCHN * NI) {
            x = d_in[i];
        } else if (sz == WID) {
            if (!ia0) ia0 = (const int*)d_in[i]; else ib0 = (const int*)d_in[i];
        } else if (sz == WID * 2) {
            ng0 = d_in[i];
        } else if (sz == NHID * WID) {
            if (!iah) iah = (const int*)d_in[i]; else ibh = (const int*)d_in[i];
        } else if (sz == NHID * WID * 2) {
            ngh = d_in[i];
        }
    }
    float* out = (float*)d_out;

    static bool attr_set = false;
    if (!attr_set) {
        cudaFuncSetAttribute(fused_k, cudaFuncAttributeMaxDynamicSharedMemorySize,
                             SM_BYTES);
        attr_set = true;
    }

    prep_idx_k<<<(NLAYERS * WIDP + 255) / 256, 256>>>(x, ia0, ib0, ng0, iah, ibh, ngh);

    // fused_k with Programmatic Dependent Launch: starts while prep runs,
    // joins via cudaGridDependencySynchronize() before reading g_gidx.
    cudaLaunchConfig_t cfg = {};
    cfg.gridDim = dim3(NSLICE, 1, 1);
    cfg.blockDim = dim3(1024, 1, 1);
    cfg.dynamicSmemBytes = SM_BYTES;
    cfg.stream = 0;
    cudaLaunchAttribute attrs[1];
    attrs[0].id = cudaLaunchAttributeProgrammaticStreamSerialization;
    attrs[0].val.programmaticStreamSerializationAllowed = 1;
    cfg.attrs = attrs;
    cfg.numAttrs = 1;
    cudaLaunchKernelEx(&cfg, fused_k, x, out);
}